// round 14
// baseline (speedup 1.0000x reference)
#include <cuda_runtime.h>
#include <cuda_fp16.h>
#include <cstdint>
#include <cstddef>
#include <math.h>

#define BB   16
#define NQ   1024
#define MKV  1024
#define DD   768
#define SCALE 0.03608439182435161f   // 768^-0.5

// ---------------- scratch (device globals) ----------------
__device__ __half g_Ah[2][DD * DD], g_Al[2][DD * DD];
__device__ float g_Apart[2][4][DD * DD];
__device__ __half g_UTh[DD * DD], g_UTl[DD * DD];
__device__ __half g_UscTh[2][DD * DD], g_UscTl[2][DD * DD];
__device__ __half g_xh[BB * NQ * DD];
__device__ __half g_yh[BB * MKV * DD];
__device__ __half g_xkh[2][BB * NQ * DD];
__device__ float g_pos[NQ * MKV];
__device__ float g_s[(size_t)BB * 2 * NQ * MKV];
__device__ __half g_ach[(size_t)BB * NQ * MKV];
__device__ int g_same;    // 1 iff S1 == S2 exactly
__device__ int g_ident;   // 1 iff S1 == S2 == 1 -> A = U^T U = I, x_k = x

// ---------------- PTX helpers ----------------
__device__ __forceinline__ unsigned u32smem(const void* p) {
    return (unsigned)__cvta_generic_to_shared(p);
}
#define CP16(dst, src) asm volatile("cp.async.cg.shared.global [%0], [%1], 16;\n" :: "r"(dst), "l"(src))
#define CPCOMMIT() asm volatile("cp.async.commit_group;\n" ::: "memory")
#define CPWAIT1() asm volatile("cp.async.wait_group 1;\n" ::: "memory")
#define LDSM4(R0,R1,R2,R3,addr) \
    asm volatile("ldmatrix.sync.aligned.m8n8.x4.shared.b16 {%0,%1,%2,%3}, [%4];" \
                 : "=r"(R0),"=r"(R1),"=r"(R2),"=r"(R3) : "r"(addr))
#define LDSM4T(R0,R1,R2,R3,addr) \
    asm volatile("ldmatrix.sync.aligned.m8n8.x4.trans.shared.b16 {%0,%1,%2,%3}, [%4];" \
                 : "=r"(R0),"=r"(R1),"=r"(R2),"=r"(R3) : "r"(addr))
#define MMA(C,A,B) \
    asm volatile("mma.sync.aligned.m16n8k16.row.col.f32.f16.f16.f32 " \
                 "{%0,%1,%2,%3},{%4,%5,%6,%7},{%8,%9},{%0,%1,%2,%3};" \
                 : "+f"((C)[0]),"+f"((C)[1]),"+f"((C)[2]),"+f"((C)[3]) \
                 : "r"((A)[0]),"r"((A)[1]),"r"((A)[2]),"r"((A)[3]),"r"((B)[0]),"r"((B)[1]))

__device__ __forceinline__ void split2(float a, float b, __half2& hi, __half2& lo) {
    __half h0 = __float2half_rn(a), h1 = __float2half_rn(b);
    __half l0 = __float2half_rn(a - __half2float(h0));
    __half l1 = __float2half_rn(b - __half2float(h1));
    hi = __halves2half2(h0, h1);
    lo = __halves2half2(l0, l1);
}

// ---------------- fp16-split HMMA mainloop, K-chunk 32 (general: TERMS 2/3) ----------------
template<bool BT, int TERMS>
__device__ __forceinline__ void gemm_main(
    const __half* __restrict__ Ah, const __half* __restrict__ Al, int lda,
    const __half* __restrict__ Bh, const __half* __restrict__ Bl, int ldb,
    int K, int row0, int col0, float acc[2][4][4])
{
    extern __shared__ char smc[];
    const unsigned BSTG = BT ? 8704u : 10240u;
    const unsigned oAl = 30720u;
    const unsigned oBh = (TERMS == 3) ? 61440u : 30720u;
    unsigned sb = u32smem(smc);
    int tid = threadIdx.x;
    int KT = K >> 5;

    auto load_stage = [&](int s, int kt) {
        if (kt < KT) {
            int k0 = kt << 5;
            {
                int rr = tid >> 2, ch = tid & 3;
                size_t go = (size_t)(row0 + rr) * lda + k0 + ch * 8;
                unsigned d = sb + (unsigned)(s * 10240 + rr * 80 + ch * 16);
                CP16(d, Ah + go);
                if (TERMS == 3) { CP16(d + oAl, Al + go); }
            }
            if (BT) {
                int kr = tid >> 4, ch = tid & 15;
                size_t go = (size_t)(k0 + kr) * ldb + col0 + ch * 8;
                unsigned d = sb + oBh + (unsigned)(s * 8704 + kr * 272 + ch * 16);
                CP16(d, Bh + go);
                if (TERMS >= 2) { CP16(d + 3u * 8704u, Bl + go); }
            } else {
                int rr = tid >> 2, ch = tid & 3;
                size_t go = (size_t)(col0 + rr) * ldb + k0 + ch * 8;
                unsigned d = sb + oBh + (unsigned)(s * 10240 + rr * 80 + ch * 16);
                CP16(d, Bh + go);
                if (TERMS >= 2) { CP16(d + 3u * 10240u, Bl + go); }
            }
        }
        CPCOMMIT();
    };

    load_stage(0, 0);
    load_stage(1, 1);

    int lane = tid & 31, wid = tid >> 5;
    int wm = wid & 3, wn = wid >> 2;
    int r = lane & 7, sel = lane >> 3, sx = sel & 1, sy = sel >> 1;

    for (int kt = 0; kt < KT; ++kt) {
        CPWAIT1();
        __syncthreads();
        load_stage((kt + 2) % 3, kt + 2);
        int s = kt % 3;
        unsigned aBase = sb + (unsigned)(s * 10240);
        unsigned bBase = sb + oBh + (unsigned)s * BSTG;
#pragma unroll
        for (int h = 0; h < 2; ++h) {
            unsigned ah[2][4], al[2][4], bh[4][2], bl[4][2];
#pragma unroll
            for (int mt = 0; mt < 2; ++mt) {
                unsigned off = (unsigned)((wm * 32 + mt * 16 + r + sx * 8) * 80 + h * 32 + sy * 16);
                LDSM4(ah[mt][0], ah[mt][1], ah[mt][2], ah[mt][3], aBase + off);
                if (TERMS == 3) {
                    LDSM4(al[mt][0], al[mt][1], al[mt][2], al[mt][3], aBase + oAl + off);
                }
            }
#pragma unroll
            for (int p = 0; p < 2; ++p) {
                unsigned t0, t1, t2, t3;
                if (BT) {
                    unsigned off = (unsigned)((h * 16 + r + sx * 8) * 272 + (wn * 32 + p * 16 + sy * 8) * 2);
                    LDSM4T(t0, t1, t2, t3, bBase + off);
                    bh[2*p][0] = t0; bh[2*p][1] = t1; bh[2*p+1][0] = t2; bh[2*p+1][1] = t3;
                    if (TERMS >= 2) {
                        LDSM4T(t0, t1, t2, t3, bBase + 3u * 8704u + off);
                        bl[2*p][0] = t0; bl[2*p][1] = t1; bl[2*p+1][0] = t2; bl[2*p+1][1] = t3;
                    }
                } else {
                    unsigned off = (unsigned)((wn * 32 + p * 16 + r + sy * 8) * 80 + h * 32 + sx * 16);
                    LDSM4(t0, t1, t2, t3, bBase + off);
                    bh[2*p][0] = t0; bh[2*p][1] = t1; bh[2*p+1][0] = t2; bh[2*p+1][1] = t3;
                    if (TERMS >= 2) {
                        LDSM4(t0, t1, t2, t3, bBase + 3u * 10240u + off);
                        bl[2*p][0] = t0; bl[2*p][1] = t1; bl[2*p+1][0] = t2; bl[2*p+1][1] = t3;
                    }
                }
            }
#pragma unroll
            for (int mt = 0; mt < 2; ++mt)
#pragma unroll
                for (int nt = 0; nt < 4; ++nt) {
                    MMA(acc[mt][nt], ah[mt], bh[nt]);
                    if (TERMS >= 2) { MMA(acc[mt][nt], ah[mt], bl[nt]); }
                    if (TERMS == 3) { MMA(acc[mt][nt], al[mt], bh[nt]); }
                }
        }
    }
}

// ---------------- 1-term HMMA mainloop, K-chunk 64 (half the barriers) ----------------
// smem: A stage 128 rows x 144B = 18432 (3 stages, base 0)
//       B NT stage 18432 @55296 ; B BT stage 64 rows x 272B = 17408 @55296
template<bool BT>
__device__ __forceinline__ void gemm64_1t(
    const __half* __restrict__ A, int lda,
    const __half* __restrict__ B, int ldb,
    int K, int row0, int col0, float acc[2][4][4])
{
    extern __shared__ char smc[];
    const unsigned ASTG = 18432u;
    const unsigned BSTG = BT ? 17408u : 18432u;
    const unsigned oB = 3u * ASTG;   // 55296
    unsigned sb = u32smem(smc);
    int tid = threadIdx.x;
    int KT = K >> 6;

    auto load_stage = [&](int s, int kt) {
        if (kt < KT) {
            int k0 = kt << 6;
#pragma unroll
            for (int i = 0; i < 2; ++i) {    // A: 1024 16B-chunks, 2/thread
                int c = tid * 2 + i;
                int rr = c >> 3, u = c & 7;
                size_t go = (size_t)(row0 + rr) * lda + k0 + u * 8;
                CP16(sb + (unsigned)(s * (int)ASTG + rr * 144 + u * 16), A + go);
            }
            if (BT) {
#pragma unroll
                for (int i = 0; i < 2; ++i) {  // B: 64 rows x 256B = 1024 chunks
                    int c = tid * 2 + i;
                    int kr = c >> 4, ch = c & 15;
                    size_t go = (size_t)(k0 + kr) * ldb + col0 + ch * 8;
                    CP16(sb + oB + (unsigned)(s * (int)BSTG + kr * 272 + ch * 16), B + go);
                }
            } else {
#pragma unroll
                for (int i = 0; i < 2; ++i) {
                    int c = tid * 2 + i;
                    int rr = c >> 3, u = c & 7;
                    size_t go = (size_t)(col0 + rr) * ldb + k0 + u * 8;
                    CP16(sb + oB + (unsigned)(s * (int)BSTG + rr * 144 + u * 16), B + go);
                }
            }
        }
        CPCOMMIT();
    };

    load_stage(0, 0);
    load_stage(1, 1);

    int lane = tid & 31, wid = tid >> 5;
    int wm = wid & 3, wn = wid >> 2;
    int r = lane & 7, sel = lane >> 3, sx = sel & 1, sy = sel >> 1;

    for (int kt = 0; kt < KT; ++kt) {
        CPWAIT1();
        __syncthreads();
        load_stage((kt + 2) % 3, kt + 2);
        int s = kt % 3;
        unsigned aBase = sb + (unsigned)s * ASTG;
        unsigned bBase = sb + oB + (unsigned)s * BSTG;
#pragma unroll
        for (int h = 0; h < 4; ++h) {      // 4 x K16 per chunk
            unsigned ah[2][4], bh[4][2];
#pragma unroll
            for (int mt = 0; mt < 2; ++mt) {
                unsigned off = (unsigned)((wm * 32 + mt * 16 + r + sx * 8) * 144 + h * 32 + sy * 16);
                LDSM4(ah[mt][0], ah[mt][1], ah[mt][2], ah[mt][3], aBase + off);
            }
#pragma unroll
            for (int p = 0; p < 2; ++p) {
                unsigned t0, t1, t2, t3;
                if (BT) {
                    unsigned off = (unsigned)((h * 16 + r + sx * 8) * 272 + (wn * 32 + p * 16 + sy * 8) * 2);
                    LDSM4T(t0, t1, t2, t3, bBase + off);
                } else {
                    unsigned off = (unsigned)((wn * 32 + p * 16 + r + sy * 8) * 144 + h * 32 + sx * 16);
                    LDSM4(t0, t1, t2, t3, bBase + off);
                }
                bh[2*p][0] = t0; bh[2*p][1] = t1; bh[2*p+1][0] = t2; bh[2*p+1][1] = t3;
            }
#pragma unroll
            for (int mt = 0; mt < 2; ++mt)
#pragma unroll
                for (int nt = 0; nt < 4; ++nt)
                    MMA(acc[mt][nt], ah[mt], bh[nt]);
        }
    }
}

// ---------------- small kernels ----------------
__global__ void k_flag(const float* __restrict__ S1, const float* __restrict__ S2) {
    __shared__ int ok, one;
    if (threadIdx.x == 0) { ok = 1; one = 1; }
    __syncthreads();
    for (int i = threadIdx.x; i < DD; i += blockDim.x) {
        float a = S1[i], b = S2[i];
        if (a != b) atomicAnd(&ok, 0);
        if (a != 1.0f || b != 1.0f) atomicAnd(&one, 0);
    }
    __syncthreads();
    if (threadIdx.x == 0) { g_same = ok; g_ident = one; }
}

// merged hi-only convert for x and y (grid.y selects)
__global__ void k_cvt2(const float4* __restrict__ xs, const float4* __restrict__ ys,
                       __half2* __restrict__ dx, __half2* __restrict__ dy, int n4) {
    int i = blockIdx.x * blockDim.x + threadIdx.x;
    if (i >= n4) return;
    const float4* s = blockIdx.y ? ys : xs;
    __half2* d = blockIdx.y ? dy : dx;
    float4 v = s[i];
    d[2 * i]     = __floats2half2_rn(v.x, v.y);
    d[2 * i + 1] = __floats2half2_rn(v.z, v.w);
}

__global__ void k_prepU(const float* __restrict__ U, const float* __restrict__ S1,
                        const float* __restrict__ S2) {
    if (g_ident) return;
    __shared__ float t[32][33];
    __shared__ float s2a[32], s2b[32];
    int j0 = blockIdx.x * 32, t0 = blockIdx.y * 32;
    int tx = threadIdx.x, ty = threadIdx.y;
    if (ty == 0) {
        float s = S1[t0 + tx]; s2a[tx] = s * s;
        float q = S2[t0 + tx]; s2b[tx] = q * q;
    }
#pragma unroll
    for (int r = 0; r < 4; ++r)
        t[ty * 4 + r][tx] = U[(size_t)(t0 + ty * 4 + r) * DD + j0 + tx];
    __syncthreads();
    int same = g_same;
#pragma unroll
    for (int r = 0; r < 4; ++r) {
        int jr = ty * 4 + r;
        float v = t[tx][jr];
        size_t o = (size_t)(j0 + jr) * DD + t0 + tx;
        __half h = __float2half_rn(v);
        g_UTh[o] = h;
        g_UTl[o] = __float2half_rn(v - __half2float(h));
        float va = v * s2a[tx];
        __half ha = __float2half_rn(va);
        g_UscTh[0][o] = ha;
        g_UscTl[0][o] = __float2half_rn(va - __half2float(ha));
        if (!same) {
            float vb = v * s2b[tx];
            __half hb = __float2half_rn(vb);
            g_UscTh[1][o] = hb;
            g_UscTl[1][o] = __float2half_rn(vb - __half2float(hb));
        }
    }
}

__global__ void k_pos(const float* __restrict__ coords, const float* __restrict__ pe) {
    int n = blockIdx.x;
    int tid = threadIdx.x;
    __shared__ float red[16];
    float p[6];
#pragma unroll
    for (int c = 0; c < 6; ++c) p[c] = pe[n * 6 + c];
    float v[4];
#pragma unroll
    for (int i = 0; i < 4; ++i) {
        int m = tid + (i << 8);
        const float* cr = coords + ((size_t)n * MKV + m) * 6;
        v[i] = cr[0]*p[0] + cr[1]*p[1] + cr[2]*p[2] + cr[3]*p[3] + cr[4]*p[4] + cr[5]*p[5];
    }
    float mx = fmaxf(fmaxf(v[0], v[1]), fmaxf(v[2], v[3]));
#pragma unroll
    for (int o = 16; o; o >>= 1) mx = fmaxf(mx, __shfl_xor_sync(0xffffffffu, mx, o));
    int w = tid >> 5, lane = tid & 31;
    if (lane == 0) red[w] = mx;
    __syncthreads();
    mx = red[0];
#pragma unroll
    for (int i = 1; i < 8; ++i) mx = fmaxf(mx, red[i]);
    __syncthreads();
    float e = 0.f;
#pragma unroll
    for (int i = 0; i < 4; ++i) { v[i] = __expf(v[i] - mx); e += v[i]; }
#pragma unroll
    for (int o = 16; o; o >>= 1) e += __shfl_xor_sync(0xffffffffu, e, o);
    if (lane == 0) red[w] = e;
    __syncthreads();
    e = 0.f;
#pragma unroll
    for (int i = 0; i < 8; ++i) e += red[i];
    float rinv = __frcp_rn(e);
#pragma unroll
    for (int i = 0; i < 4; ++i) {
        int m = tid + (i << 8);
        g_pos[(size_t)n * MKV + m] = v[i] * rinv;
    }
}

// ---------------- GEMM kernels ----------------

// A_k partials: split-K (4x192), 3-term
__global__ void __launch_bounds__(512, 1) k_buildA() {
    if (g_ident) return;
    int z = blockIdx.z;
    int k2 = z >> 2, ks = z & 3;
    if (k2 == 1 && g_same) return;
    int row0 = blockIdx.y << 7, col0 = blockIdx.x << 7;
    float acc[2][4][4] = {};
    gemm_main<false, 3>(g_UscTh[k2] + ks * 192, g_UscTl[k2] + ks * 192, DD,
                        g_UTh + ks * 192, g_UTl + ks * 192, DD,
                        192, row0, col0, acc);
    int lane = threadIdx.x & 31, wid = threadIdx.x >> 5;
    int wm = wid & 3, wn = wid >> 2, g = lane >> 2, tg = lane & 3;
    float* P = g_Apart[k2][ks];
#pragma unroll
    for (int mt = 0; mt < 2; ++mt)
#pragma unroll
        for (int nt = 0; nt < 4; ++nt) {
            int row = row0 + wm * 32 + mt * 16 + g;
            int col = col0 + wn * 32 + nt * 8 + tg * 2;
#pragma unroll
            for (int hh = 0; hh < 2; ++hh) {
                float2 v = make_float2(acc[mt][nt][2 * hh], acc[mt][nt][2 * hh + 1]);
                *(float2*)(P + (size_t)(row + hh * 8) * DD + col) = v;
            }
        }
}

__global__ void k_cvtA() {
    if (g_ident) return;
    int k2 = blockIdx.y;
    if (k2 == 1 && g_same) return;
    int i = blockIdx.x * blockDim.x + threadIdx.x;
    int idx = i * 2;
    float2 a = *(const float2*)(g_Apart[k2][0] + idx);
    float2 b = *(const float2*)(g_Apart[k2][1] + idx);
    float2 c = *(const float2*)(g_Apart[k2][2] + idx);
    float2 d = *(const float2*)(g_Apart[k2][3] + idx);
    float v0 = a.x + b.x + c.x + d.x;
    float v1 = a.y + b.y + c.y + d.y;
    __half2 hi, lo;
    split2(v0, v1, hi, lo);
    *(__half2*)(g_Ah[k2] + idx) = hi;
    *(__half2*)(g_Al[k2] + idx) = lo;
}

// x_k = x @ A_k — 2-term (general path only)
__global__ void __launch_bounds__(512, 2) k_xk() {
    if (g_ident) return;
    int z = blockIdx.z;
    if (z == 1 && g_same) return;
    int row0 = blockIdx.y << 7, col0 = blockIdx.x << 7;
    float acc[2][4][4] = {};
    gemm_main<false, 2>(g_xh, g_xh, DD,
                        g_Ah[z], g_Al[z], DD,
                        DD, row0, col0, acc);
    int lane = threadIdx.x & 31, wid = threadIdx.x >> 5;
    int wm = wid & 3, wn = wid >> 2, g = lane >> 2, tg = lane & 3;
    __half* Ch = g_xkh[z];
#pragma unroll
    for (int mt = 0; mt < 2; ++mt)
#pragma unroll
        for (int nt = 0; nt < 4; ++nt) {
            int row = row0 + wm * 32 + mt * 16 + g;
            int col = col0 + wn * 32 + nt * 8 + tg * 2;
#pragma unroll
            for (int hh = 0; hh < 2; ++hh) {
                size_t idx = (size_t)(row + hh * 8) * DD + col;
                *(__half2*)(Ch + idx) =
                    __floats2half2_rn(acc[mt][nt][2 * hh], acc[mt][nt][2 * hh + 1]);
            }
        }
}

// scores (NT): s = scale * x_k[b] @ y[b]^T — 1-term, chunk 64
__global__ void __launch_bounds__(512, 2) k_scores() {
    int z = blockIdx.z; int b = z >> 1; int k2 = z & 1;
    if (k2 == 1 && g_same) return;
    int row0 = blockIdx.y << 7, col0 = blockIdx.x << 7;
    const __half* A = g_ident ? (g_xh + (size_t)b * NQ * DD)
                              : (g_xkh[k2] + (size_t)b * NQ * DD);
    float acc[2][4][4] = {};
    gemm64_1t<false>(A, DD, g_yh + (size_t)b * MKV * DD, DD, DD, row0, col0, acc);
    int lane = threadIdx.x & 31, wid = threadIdx.x >> 5;
    int wm = wid & 3, wn = wid >> 2, g = lane >> 2, tg = lane & 3;
    float* C = g_s + (size_t)z * NQ * MKV;
#pragma unroll
    for (int mt = 0; mt < 2; ++mt)
#pragma unroll
        for (int nt = 0; nt < 4; ++nt) {
            int row = row0 + wm * 32 + mt * 16 + g;
            int col = col0 + wn * 32 + nt * 8 + tg * 2;
#pragma unroll
            for (int hh = 0; hh < 2; ++hh) {
                float2 v = make_float2(acc[mt][nt][2 * hh] * SCALE, acc[mt][nt][2 * hh + 1] * SCALE);
                *(float2*)(C + (size_t)(row + hh * 8) * MKV + col) = v;
            }
        }
}

// out = attn_c @ y (NN) — 1-term, chunk 64
__global__ void __launch_bounds__(512, 2) k_av(float* __restrict__ out) {
    int b = blockIdx.z;
    int row0 = blockIdx.y << 7, col0 = blockIdx.x << 7;
    float acc[2][4][4] = {};
    gemm64_1t<true>(g_ach + (size_t)b * NQ * MKV, MKV,
                    g_yh + (size_t)b * MKV * DD, DD,
                    MKV, row0, col0, acc);
    int lane = threadIdx.x & 31, wid = threadIdx.x >> 5;
    int wm = wid & 3, wn = wid >> 2, g = lane >> 2, tg = lane & 3;
    float* C = out + (size_t)b * NQ * DD;
#pragma unroll
    for (int mt = 0; mt < 2; ++mt)
#pragma unroll
        for (int nt = 0; nt < 4; ++nt) {
            int row = row0 + wm * 32 + mt * 16 + g;
            int col = col0 + wn * 32 + nt * 8 + tg * 2;
#pragma unroll
            for (int hh = 0; hh < 2; ++hh) {
                float2 v = make_float2(acc[mt][nt][2 * hh], acc[mt][nt][2 * hh + 1]);
                *(float2*)(C + (size_t)(row + hh * 8) * DD + col) = v;
            }
        }
}

// ---------------- K4: softmax + mix + entropy + route ----------------
__device__ __forceinline__ void blockReduce2(float& a, float& b, bool domax, float* red) {
#pragma unroll
    for (int o = 16; o; o >>= 1) {
        float ta = __shfl_xor_sync(0xffffffffu, a, o);
        float tb = __shfl_xor_sync(0xffffffffu, b, o);
        if (domax) { a = fmaxf(a, ta); b = fmaxf(b, tb); }
        else       { a += ta;          b += tb; }
    }
    int w = threadIdx.x >> 5, lane = threadIdx.x & 31;
    __syncthreads();
    if (lane == 0) { red[w] = a; red[8 + w] = b; }
    __syncthreads();
    a = red[0]; b = red[8];
#pragma unroll
    for (int i = 1; i < 8; ++i) {
        if (domax) { a = fmaxf(a, red[i]); b = fmaxf(b, red[8 + i]); }
        else       { a += red[i];          b += red[8 + i]; }
    }
}

__global__ void k_route(const float* __restrict__ gate, const float* __restrict__ temp,
                        float* __restrict__ heat_out) {
    int n = blockIdx.x, b = blockIdx.y;
    int tid = threadIdx.x;
    __shared__ float red[16];
    int same = g_same;
    const float* s1 = g_s + ((size_t)(b * 2 + 0) * NQ + n) * MKV;
    const float* s2 = g_s + ((size_t)(b * 2 + 1) * NQ + n) * MKV;
    const float* pp = g_pos + (size_t)n * MKV;
    int base = tid * 4;
    float4 V1 = *(const float4*)(s1 + base);
    float4 PV = *(const float4*)(pp + base);
    float v1[4] = {V1.x, V1.y, V1.z, V1.w};
    float pv[4] = {PV.x, PV.y, PV.z, PV.w};
    float gg = gate[0];
    float gsig = 1.f / (1.f + __expf(-gg));
    float og = 1.f - gsig;
    float tt = temp[0];
    size_t rowoff = ((size_t)b * NQ + n) * MKV;

    if (same) {
        float m1 = -1e30f, dummy = -1e30f;
#pragma unroll
        for (int i = 0; i < 4; ++i) m1 = fmaxf(m1, v1[i]);
        blockReduce2(m1, dummy, true, red);
        float e1 = 0.f, d2 = 0.f;
#pragma unroll
        for (int i = 0; i < 4; ++i) { v1[i] = __expf(v1[i] - m1); e1 += v1[i]; }
        blockReduce2(e1, d2, false, red);
        float r1 = __frcp_rn(e1);
        float ent1 = 0.f, d3 = 0.f;
#pragma unroll
        for (int i = 0; i < 4; ++i) {
            float a1 = og * v1[i] * r1 + gsig * pv[i];
            v1[i] = a1;
            ent1 -= a1 * __logf(a1 + 1e-8f);
        }
        blockReduce2(ent1, d3, false, red);
        float h1 = 2.f - 2.f / (1.f + __expf(-tt * ent1));
        if (tid == 0) heat_out[(size_t)b * NQ + n] = h1;
        *(__half2*)(g_ach + rowoff + base)     = __floats2half2_rn(v1[0], v1[1]);
        *(__half2*)(g_ach + rowoff + base + 2) = __floats2half2_rn(v1[2], v1[3]);
        return;
    }

    float4 V2 = *(const float4*)(s2 + base);
    float v2[4] = {V2.x, V2.y, V2.z, V2.w};
    float m1 = -1e30f, m2 = -1e30f;
#pragma unroll
    for (int i = 0; i < 4; ++i) { m1 = fmaxf(m1, v1[i]); m2 = fmaxf(m2, v2[i]); }
    blockReduce2(m1, m2, true, red);
    float e1 = 0.f, e2 = 0.f;
#pragma unroll
    for (int i = 0; i < 4; ++i) {
        v1[i] = __expf(v1[i] - m1); e1 += v1[i];
        v2[i] = __expf(v2[i] - m2); e2 += v2[i];
    }
    blockReduce2(e1, e2, false, red);
    float r1 = __frcp_rn(e1), r2 = __frcp_rn(e2);
    float ent1 = 0.f, ent2 = 0.f;
#pragma unroll
    for (int i = 0; i < 4; ++i) {
        float a1 = og * v1[i] * r1 + gsig * pv[i];
        float a2 = og * v2[i] * r2 + gsig * pv[i];
        v1[i] = a1; v2[i] = a2;
        ent1 -= a1 * __logf(a1 + 1e-8f);
        ent2 -= a2 * __logf(a2 + 1e-8f);
    }
    blockReduce2(ent1, ent2, false, red);
    float h1 = 2.f - 2.f / (1.f + __expf(-tt * ent1));
    float h2 = 2.f - 2.f / (1.f + __expf(-tt * ent2));
    bool fg = (h1 >= h2);
    if (tid == 0) heat_out[(size_t)b * NQ + n] = fg ? h1 : h2;
    float a0 = fg ? v1[0] : v2[0], a1 = fg ? v1[1] : v2[1];
    float a2 = fg ? v1[2] : v2[2], a3 = fg ? v1[3] : v2[3];
    *(__half2*)(g_ach + rowoff + base)     = __floats2half2_rn(a0, a1);
    *(__half2*)(g_ach + rowoff + base + 2) = __floats2half2_rn(a2, a3);
}

// ---------------- launch ----------------
extern "C" void kernel_launch(void* const* d_in, const int* in_sizes, int n_in,
                              void* d_out, int out_size) {
    const float* x      = (const float*)d_in[0];
    const float* y      = (const float*)d_in[1];
    const float* coords = (const float*)d_in[2];
    const float* U      = (const float*)d_in[3];
    const float* S1     = (const float*)d_in[4];
    const float* S2     = (const float*)d_in[5];
    const float* gating = (const float*)d_in[6];
    const float* temp   = (const float*)d_in[7];
    const float* pe     = (const float*)d_in[8];
    float* out  = (float*)d_out;                 // [B,N,D]
    float* heat = out + (size_t)BB * NQ * DD;    // [B,N,1]

    const int SM3    = 122880;  // 3-term NT chunk32
    const int SM2    = 92160;   // 2-term NT chunk32
    const int SM64NT = 110592;  // 1-term NT chunk64: 3*(18432+18432)
    const int SM64BT = 107520;  // 1-term BT chunk64: 3*18432 + 3*17408
    cudaFuncSetAttribute(k_buildA, cudaFuncAttributeMaxDynamicSharedMemorySize, SM3);
    cudaFuncSetAttribute(k_xk,     cudaFuncAttributeMaxDynamicSharedMemorySize, SM2);
    cudaFuncSetAttribute(k_scores, cudaFuncAttributeMaxDynamicSharedMemorySize, SM64NT);
    cudaFuncSetAttribute(k_av,     cudaFuncAttributeMaxDynamicSharedMemorySize, SM64BT);

    __half *xh, *yh;
    cudaGetSymbolAddress((void**)&xh, g_xh);
    cudaGetSymbolAddress((void**)&yh, g_yh);

    int n4 = BB * NQ * DD / 4;
    k_flag<<<1, 256>>>(S1, S2);
    k_prepU<<<dim3(DD / 32, DD / 32), dim3(32, 8)>>>(U, S1, S2);
    k_cvt2<<<dim3((n4 + 255) / 256, 2), 256>>>((const float4*)x, (const float4*)y,
                                               (__half2*)xh, (__half2*)yh, n4);
    k_buildA<<<dim3(DD / 128, DD / 128, 8), 512, SM3>>>();
    k_cvtA<<<dim3(DD * DD / 512, 2), 256>>>();
    k_xk    <<<dim3(DD / 128, BB * NQ / 128, 2), 512, SM2>>>();
    k_pos<<<dim3(NQ), 256>>>(coords, pe);
    k_scores<<<dim3(MKV / 128, NQ / 128, BB * 2), 512, SM64NT>>>();
    k_route <<<dim3(NQ, BB), 256>>>(gating, temp, heat);
    k_av    <<<dim3(DD / 128, NQ / 128, BB), 512, SM64BT>>>(out);
}

// round 15
// speedup vs baseline: 1.0740x; 1.0740x over previous
#include <cuda_runtime.h>
#include <cuda_fp16.h>
#include <cstdint>
#include <cstddef>
#include <math.h>

#define BB   16
#define NQ   1024
#define MKV  1024
#define DD   768
#define SCALE 0.03608439182435161f   // 768^-0.5

// ---------------- scratch (device globals) ----------------
__device__ __half g_Ah[2][DD * DD], g_Al[2][DD * DD];
__device__ float g_Apart[2][4][DD * DD];
__device__ __half g_UTh[DD * DD], g_UTl[DD * DD];
__device__ __half g_UscTh[2][DD * DD], g_UscTl[2][DD * DD];
__device__ __half g_xh[BB * NQ * DD];
__device__ __half g_yh[BB * MKV * DD];
__device__ __half g_xkh[2][BB * NQ * DD];
__device__ float g_pos[NQ * MKV];
__device__ float g_s[(size_t)BB * 2 * NQ * MKV];
__device__ __half g_ach[(size_t)BB * NQ * MKV];
__device__ int g_same;    // 1 iff S1 == S2 exactly
__device__ int g_ident;   // 1 iff S1 == S2 == 1 -> A = U^T U = I (QR-orthogonal U), x_k = x

// ---------------- PTX helpers ----------------
__device__ __forceinline__ unsigned u32smem(const void* p) {
    return (unsigned)__cvta_generic_to_shared(p);
}
#define CP16(dst, src) asm volatile("cp.async.cg.shared.global [%0], [%1], 16;\n" :: "r"(dst), "l"(src))
#define CPCOMMIT() asm volatile("cp.async.commit_group;\n" ::: "memory")
#define CPWAIT1() asm volatile("cp.async.wait_group 1;\n" ::: "memory")
#define LDSM4(R0,R1,R2,R3,addr) \
    asm volatile("ldmatrix.sync.aligned.m8n8.x4.shared.b16 {%0,%1,%2,%3}, [%4];" \
                 : "=r"(R0),"=r"(R1),"=r"(R2),"=r"(R3) : "r"(addr))
#define LDSM4T(R0,R1,R2,R3,addr) \
    asm volatile("ldmatrix.sync.aligned.m8n8.x4.trans.shared.b16 {%0,%1,%2,%3}, [%4];" \
                 : "=r"(R0),"=r"(R1),"=r"(R2),"=r"(R3) : "r"(addr))
#define MMA(C,A,B) \
    asm volatile("mma.sync.aligned.m16n8k16.row.col.f32.f16.f16.f32 " \
                 "{%0,%1,%2,%3},{%4,%5,%6,%7},{%8,%9},{%0,%1,%2,%3};" \
                 : "+f"((C)[0]),"+f"((C)[1]),"+f"((C)[2]),"+f"((C)[3]) \
                 : "r"((A)[0]),"r"((A)[1]),"r"((A)[2]),"r"((A)[3]),"r"((B)[0]),"r"((B)[1]))

__device__ __forceinline__ void split2(float a, float b, __half2& hi, __half2& lo) {
    __half h0 = __float2half_rn(a), h1 = __float2half_rn(b);
    __half l0 = __float2half_rn(a - __half2float(h0));
    __half l1 = __float2half_rn(b - __half2float(h1));
    hi = __halves2half2(h0, h1);
    lo = __halves2half2(l0, l1);
}

// ---------------- fp16-split HMMA mainloop, K-chunk 32 ----------------
// Block tile 128x128, 512 threads (16 warps, 4Mx4N), 3-stage cp.async pipeline.
// TERMS==1: C = Ah*Bh.  TERMS==2: + Ah*Bl.  TERMS==3: + Al*Bh.

template<bool BT, int TERMS>
__device__ __forceinline__ void gemm_main(
    const __half* __restrict__ Ah, const __half* __restrict__ Al, int lda,
    const __half* __restrict__ Bh, const __half* __restrict__ Bl, int ldb,
    int K, int row0, int col0, float acc[2][4][4])
{
    extern __shared__ char smc[];
    const unsigned BSTG = BT ? 8704u : 10240u;
    const unsigned oAl = 30720u;
    const unsigned oBh = (TERMS == 3) ? 61440u : 30720u;
    unsigned sb = u32smem(smc);
    int tid = threadIdx.x;
    int KT = K >> 5;

    auto load_stage = [&](int s, int kt) {
        if (kt < KT) {
            int k0 = kt << 5;
            {
                int rr = tid >> 2, ch = tid & 3;
                size_t go = (size_t)(row0 + rr) * lda + k0 + ch * 8;
                unsigned d = sb + (unsigned)(s * 10240 + rr * 80 + ch * 16);
                CP16(d, Ah + go);
                if (TERMS == 3) { CP16(d + oAl, Al + go); }
            }
            if (BT) {
                int kr = tid >> 4, ch = tid & 15;
                size_t go = (size_t)(k0 + kr) * ldb + col0 + ch * 8;
                unsigned d = sb + oBh + (unsigned)(s * 8704 + kr * 272 + ch * 16);
                CP16(d, Bh + go);
                if (TERMS >= 2) { CP16(d + 3u * 8704u, Bl + go); }
            } else {
                int rr = tid >> 2, ch = tid & 3;
                size_t go = (size_t)(col0 + rr) * ldb + k0 + ch * 8;
                unsigned d = sb + oBh + (unsigned)(s * 10240 + rr * 80 + ch * 16);
                CP16(d, Bh + go);
                if (TERMS >= 2) { CP16(d + 3u * 10240u, Bl + go); }
            }
        }
        CPCOMMIT();
    };

    load_stage(0, 0);
    load_stage(1, 1);

    int lane = tid & 31, wid = tid >> 5;
    int wm = wid & 3, wn = wid >> 2;
    int r = lane & 7, sel = lane >> 3, sx = sel & 1, sy = sel >> 1;

    for (int kt = 0; kt < KT; ++kt) {
        CPWAIT1();
        __syncthreads();
        load_stage((kt + 2) % 3, kt + 2);
        int s = kt % 3;
        unsigned aBase = sb + (unsigned)(s * 10240);
        unsigned bBase = sb + oBh + (unsigned)s * BSTG;
#pragma unroll
        for (int h = 0; h < 2; ++h) {
            unsigned ah[2][4], al[2][4], bh[4][2], bl[4][2];
#pragma unroll
            for (int mt = 0; mt < 2; ++mt) {
                unsigned off = (unsigned)((wm * 32 + mt * 16 + r + sx * 8) * 80 + h * 32 + sy * 16);
                LDSM4(ah[mt][0], ah[mt][1], ah[mt][2], ah[mt][3], aBase + off);
                if (TERMS == 3) {
                    LDSM4(al[mt][0], al[mt][1], al[mt][2], al[mt][3], aBase + oAl + off);
                }
            }
#pragma unroll
            for (int p = 0; p < 2; ++p) {
                unsigned t0, t1, t2, t3;
                if (BT) {
                    unsigned off = (unsigned)((h * 16 + r + sx * 8) * 272 + (wn * 32 + p * 16 + sy * 8) * 2);
                    LDSM4T(t0, t1, t2, t3, bBase + off);
                    bh[2*p][0] = t0; bh[2*p][1] = t1; bh[2*p+1][0] = t2; bh[2*p+1][1] = t3;
                    if (TERMS >= 2) {
                        LDSM4T(t0, t1, t2, t3, bBase + 3u * 8704u + off);
                        bl[2*p][0] = t0; bl[2*p][1] = t1; bl[2*p+1][0] = t2; bl[2*p+1][1] = t3;
                    }
                } else {
                    unsigned off = (unsigned)((wn * 32 + p * 16 + r + sy * 8) * 80 + h * 32 + sx * 16);
                    LDSM4(t0, t1, t2, t3, bBase + off);
                    bh[2*p][0] = t0; bh[2*p][1] = t1; bh[2*p+1][0] = t2; bh[2*p+1][1] = t3;
                    if (TERMS >= 2) {
                        LDSM4(t0, t1, t2, t3, bBase + 3u * 10240u + off);
                        bl[2*p][0] = t0; bl[2*p][1] = t1; bl[2*p+1][0] = t2; bl[2*p+1][1] = t3;
                    }
                }
            }
#pragma unroll
            for (int mt = 0; mt < 2; ++mt)
#pragma unroll
                for (int nt = 0; nt < 4; ++nt) {
                    MMA(acc[mt][nt], ah[mt], bh[nt]);
                    if (TERMS >= 2) { MMA(acc[mt][nt], ah[mt], bl[nt]); }
                    if (TERMS == 3) { MMA(acc[mt][nt], al[mt], bh[nt]); }
                }
        }
    }
}

// ---------------- small kernels ----------------
__global__ void k_flag(const float* __restrict__ S1, const float* __restrict__ S2) {
    __shared__ int ok, one;
    if (threadIdx.x == 0) { ok = 1; one = 1; }
    __syncthreads();
    for (int i = threadIdx.x; i < DD; i += blockDim.x) {
        float a = S1[i], b = S2[i];
        if (a != b) atomicAnd(&ok, 0);
        if (a != 1.0f || b != 1.0f) atomicAnd(&one, 0);
    }
    __syncthreads();
    if (threadIdx.x == 0) { g_same = ok; g_ident = one; }
}

// merged hi-only convert for x and y (grid.y selects)
__global__ void k_cvt2(const float4* __restrict__ xs, const float4* __restrict__ ys,
                       __half2* __restrict__ dx, __half2* __restrict__ dy, int n4) {
    int i = blockIdx.x * blockDim.x + threadIdx.x;
    if (i >= n4) return;
    const float4* s = blockIdx.y ? ys : xs;
    __half2* d = blockIdx.y ? dy : dx;
    float4 v = s[i];
    d[2 * i]     = __floats2half2_rn(v.x, v.y);
    d[2 * i + 1] = __floats2half2_rn(v.z, v.w);
}

__global__ void k_prepU(const float* __restrict__ U, const float* __restrict__ S1,
                        const float* __restrict__ S2) {
    if (g_ident) return;
    __shared__ float t[32][33];
    __shared__ float s2a[32], s2b[32];
    int j0 = blockIdx.x * 32, t0 = blockIdx.y * 32;
    int tx = threadIdx.x, ty = threadIdx.y;
    if (ty == 0) {
        float s = S1[t0 + tx]; s2a[tx] = s * s;
        float q = S2[t0 + tx]; s2b[tx] = q * q;
    }
#pragma unroll
    for (int r = 0; r < 4; ++r)
        t[ty * 4 + r][tx] = U[(size_t)(t0 + ty * 4 + r) * DD + j0 + tx];
    __syncthreads();
    int same = g_same;
#pragma unroll
    for (int r = 0; r < 4; ++r) {
        int jr = ty * 4 + r;
        float v = t[tx][jr];
        size_t o = (size_t)(j0 + jr) * DD + t0 + tx;
        __half h = __float2half_rn(v);
        g_UTh[o] = h;
        g_UTl[o] = __float2half_rn(v - __half2float(h));
        float va = v * s2a[tx];
        __half ha = __float2half_rn(va);
        g_UscTh[0][o] = ha;
        g_UscTl[0][o] = __float2half_rn(va - __half2float(ha));
        if (!same) {
            float vb = v * s2b[tx];
            __half hb = __float2half_rn(vb);
            g_UscTh[1][o] = hb;
            g_UscTl[1][o] = __float2half_rn(vb - __half2float(hb));
        }
    }
}

__global__ void k_pos(const float* __restrict__ coords, const float* __restrict__ pe) {
    int n = blockIdx.x;
    int tid = threadIdx.x;
    __shared__ float red[16];
    float p[6];
#pragma unroll
    for (int c = 0; c < 6; ++c) p[c] = pe[n * 6 + c];
    float v[4];
#pragma unroll
    for (int i = 0; i < 4; ++i) {
        int m = tid + (i << 8);
        const float* cr = coords + ((size_t)n * MKV + m) * 6;
        v[i] = cr[0]*p[0] + cr[1]*p[1] + cr[2]*p[2] + cr[3]*p[3] + cr[4]*p[4] + cr[5]*p[5];
    }
    float mx = fmaxf(fmaxf(v[0], v[1]), fmaxf(v[2], v[3]));
#pragma unroll
    for (int o = 16; o; o >>= 1) mx = fmaxf(mx, __shfl_xor_sync(0xffffffffu, mx, o));
    int w = tid >> 5, lane = tid & 31;
    if (lane == 0) red[w] = mx;
    __syncthreads();
    mx = red[0];
#pragma unroll
    for (int i = 1; i < 8; ++i) mx = fmaxf(mx, red[i]);
    __syncthreads();
    float e = 0.f;
#pragma unroll
    for (int i = 0; i < 4; ++i) { v[i] = __expf(v[i] - mx); e += v[i]; }
#pragma unroll
    for (int o = 16; o; o >>= 1) e += __shfl_xor_sync(0xffffffffu, e, o);
    if (lane == 0) red[w] = e;
    __syncthreads();
    e = 0.f;
#pragma unroll
    for (int i = 0; i < 8; ++i) e += red[i];
    float rinv = __frcp_rn(e);
#pragma unroll
    for (int i = 0; i < 4; ++i) {
        int m = tid + (i << 8);
        g_pos[(size_t)n * MKV + m] = v[i] * rinv;
    }
}

// ---------------- GEMM kernels ----------------

// A_k partials: split-K (4x192), 3-term
__global__ void __launch_bounds__(512, 1) k_buildA() {
    if (g_ident) return;
    int z = blockIdx.z;
    int k2 = z >> 2, ks = z & 3;
    if (k2 == 1 && g_same) return;
    int row0 = blockIdx.y << 7, col0 = blockIdx.x << 7;
    float acc[2][4][4] = {};
    gemm_main<false, 3>(g_UscTh[k2] + ks * 192, g_UscTl[k2] + ks * 192, DD,
                        g_UTh + ks * 192, g_UTl + ks * 192, DD,
                        192, row0, col0, acc);
    int lane = threadIdx.x & 31, wid = threadIdx.x >> 5;
    int wm = wid & 3, wn = wid >> 2, g = lane >> 2, tg = lane & 3;
    float* P = g_Apart[k2][ks];
#pragma unroll
    for (int mt = 0; mt < 2; ++mt)
#pragma unroll
        for (int nt = 0; nt < 4; ++nt) {
            int row = row0 + wm * 32 + mt * 16 + g;
            int col = col0 + wn * 32 + nt * 8 + tg * 2;
#pragma unroll
            for (int hh = 0; hh < 2; ++hh) {
                float2 v = make_float2(acc[mt][nt][2 * hh], acc[mt][nt][2 * hh + 1]);
                *(float2*)(P + (size_t)(row + hh * 8) * DD + col) = v;
            }
        }
}

__global__ void k_cvtA() {
    if (g_ident) return;
    int k2 = blockIdx.y;
    if (k2 == 1 && g_same) return;
    int i = blockIdx.x * blockDim.x + threadIdx.x;
    int idx = i * 2;
    float2 a = *(const float2*)(g_Apart[k2][0] + idx);
    float2 b = *(const float2*)(g_Apart[k2][1] + idx);
    float2 c = *(const float2*)(g_Apart[k2][2] + idx);
    float2 d = *(const float2*)(g_Apart[k2][3] + idx);
    float v0 = a.x + b.x + c.x + d.x;
    float v1 = a.y + b.y + c.y + d.y;
    __half2 hi, lo;
    split2(v0, v1, hi, lo);
    *(__half2*)(g_Ah[k2] + idx) = hi;
    *(__half2*)(g_Al[k2] + idx) = lo;
}

// x_k = x @ A_k — 2-term (general path only)
__global__ void __launch_bounds__(512, 2) k_xk() {
    if (g_ident) return;
    int z = blockIdx.z;
    if (z == 1 && g_same) return;
    int row0 = blockIdx.y << 7, col0 = blockIdx.x << 7;
    float acc[2][4][4] = {};
    gemm_main<false, 2>(g_xh, g_xh, DD,
                        g_Ah[z], g_Al[z], DD,
                        DD, row0, col0, acc);
    int lane = threadIdx.x & 31, wid = threadIdx.x >> 5;
    int wm = wid & 3, wn = wid >> 2, g = lane >> 2, tg = lane & 3;
    __half* Ch = g_xkh[z];
#pragma unroll
    for (int mt = 0; mt < 2; ++mt)
#pragma unroll
        for (int nt = 0; nt < 4; ++nt) {
            int row = row0 + wm * 32 + mt * 16 + g;
            int col = col0 + wn * 32 + nt * 8 + tg * 2;
#pragma unroll
            for (int hh = 0; hh < 2; ++hh) {
                size_t idx = (size_t)(row + hh * 8) * DD + col;
                *(__half2*)(Ch + idx) =
                    __floats2half2_rn(acc[mt][nt][2 * hh], acc[mt][nt][2 * hh + 1]);
            }
        }
}

// scores (NT): s = scale * x_k[b] @ y[b]^T — 1-term, chunk 32
__global__ void __launch_bounds__(512, 2) k_scores() {
    int z = blockIdx.z; int b = z >> 1; int k2 = z & 1;
    if (k2 == 1 && g_same) return;
    int row0 = blockIdx.y << 7, col0 = blockIdx.x << 7;
    const __half* A = g_ident ? (g_xh + (size_t)b * NQ * DD)
                              : (g_xkh[k2] + (size_t)b * NQ * DD);
    float acc[2][4][4] = {};
    gemm_main<false, 1>(A, A, DD,
                        g_yh + (size_t)b * MKV * DD, g_yh + (size_t)b * MKV * DD, DD,
                        DD, row0, col0, acc);
    int lane = threadIdx.x & 31, wid = threadIdx.x >> 5;
    int wm = wid & 3, wn = wid >> 2, g = lane >> 2, tg = lane & 3;
    float* C = g_s + (size_t)z * NQ * MKV;
#pragma unroll
    for (int mt = 0; mt < 2; ++mt)
#pragma unroll
        for (int nt = 0; nt < 4; ++nt) {
            int row = row0 + wm * 32 + mt * 16 + g;
            int col = col0 + wn * 32 + nt * 8 + tg * 2;
#pragma unroll
            for (int hh = 0; hh < 2; ++hh) {
                float2 v = make_float2(acc[mt][nt][2 * hh] * SCALE, acc[mt][nt][2 * hh + 1] * SCALE);
                *(float2*)(C + (size_t)(row + hh * 8) * MKV + col) = v;
            }
        }
}

// out = attn_c @ y (NN) — 1-term, chunk 32
__global__ void __launch_bounds__(512, 2) k_av(float* __restrict__ out) {
    int b = blockIdx.z;
    int row0 = blockIdx.y << 7, col0 = blockIdx.x << 7;
    float acc[2][4][4] = {};
    gemm_main<true, 1>(g_ach + (size_t)b * NQ * MKV, g_ach + (size_t)b * NQ * MKV, MKV,
                       g_yh + (size_t)b * MKV * DD, g_yh + (size_t)b * MKV * DD, DD,
                       MKV, row0, col0, acc);
    int lane = threadIdx.x & 31, wid = threadIdx.x >> 5;
    int wm = wid & 3, wn = wid >> 2, g = lane >> 2, tg = lane & 3;
    float* C = out + (size_t)b * NQ * DD;
#pragma unroll
    for (int mt = 0; mt < 2; ++mt)
#pragma unroll
        for (int nt = 0; nt < 4; ++nt) {
            int row = row0 + wm * 32 + mt * 16 + g;
            int col = col0 + wn * 32 + nt * 8 + tg * 2;
#pragma unroll
            for (int hh = 0; hh < 2; ++hh) {
                float2 v = make_float2(acc[mt][nt][2 * hh], acc[mt][nt][2 * hh + 1]);
                *(float2*)(C + (size_t)(row + hh * 8) * DD + col) = v;
            }
        }
}

// ---------------- K4: softmax + mix + entropy + route ----------------
__device__ __forceinline__ void blockReduce2(float& a, float& b, bool domax, float* red) {
#pragma unroll
    for (int o = 16; o; o >>= 1) {
        float ta = __shfl_xor_sync(0xffffffffu, a, o);
        float tb = __shfl_xor_sync(0xffffffffu, b, o);
        if (domax) { a = fmaxf(a, ta); b = fmaxf(b, tb); }
        else       { a += ta;          b += tb; }
    }
    int w = threadIdx.x >> 5, lane = threadIdx.x & 31;
    __syncthreads();
    if (lane == 0) { red[w] = a; red[8 + w] = b; }
    __syncthreads();
    a = red[0]; b = red[8];
#pragma unroll
    for (int i = 1; i < 8; ++i) {
        if (domax) { a = fmaxf(a, red[i]); b = fmaxf(b, red[8 + i]); }
        else       { a += red[i];          b += red[8 + i]; }
    }
}

__global__ void k_route(const float* __restrict__ gate, const float* __restrict__ temp,
                        float* __restrict__ heat_out) {
    int n = blockIdx.x, b = blockIdx.y;
    int tid = threadIdx.x;
    __shared__ float red[16];
    int same = g_same;
    const float* s1 = g_s + ((size_t)(b * 2 + 0) * NQ + n) * MKV;
    const float* s2 = g_s + ((size_t)(b * 2 + 1) * NQ + n) * MKV;
    const float* pp = g_pos + (size_t)n * MKV;
    int base = tid * 4;
    float4 V1 = *(const float4*)(s1 + base);
    float4 PV = *(const float4*)(pp + base);
    float v1[4] = {V1.x, V1.y, V1.z, V1.w};
    float pv[4] = {PV.x, PV.y, PV.z, PV.w};
    float gg = gate[0];
    float gsig = 1.f / (1.f + __expf(-gg));
    float og = 1.f - gsig;
    float tt = temp[0];
    size_t rowoff = ((size_t)b * NQ + n) * MKV;

    if (same) {
        float m1 = -1e30f, dummy = -1e30f;
#pragma unroll
        for (int i = 0; i < 4; ++i) m1 = fmaxf(m1, v1[i]);
        blockReduce2(m1, dummy, true, red);
        float e1 = 0.f, d2 = 0.f;
#pragma unroll
        for (int i = 0; i < 4; ++i) { v1[i] = __expf(v1[i] - m1); e1 += v1[i]; }
        blockReduce2(e1, d2, false, red);
        float r1 = __frcp_rn(e1);
        float ent1 = 0.f, d3 = 0.f;
#pragma unroll
        for (int i = 0; i < 4; ++i) {
            float a1 = og * v1[i] * r1 + gsig * pv[i];
            v1[i] = a1;
            ent1 -= a1 * __logf(a1 + 1e-8f);
        }
        blockReduce2(ent1, d3, false, red);
        float h1 = 2.f - 2.f / (1.f + __expf(-tt * ent1));
        if (tid == 0) heat_out[(size_t)b * NQ + n] = h1;
        *(__half2*)(g_ach + rowoff + base)     = __floats2half2_rn(v1[0], v1[1]);
        *(__half2*)(g_ach + rowoff + base + 2) = __floats2half2_rn(v1[2], v1[3]);
        return;
    }

    float4 V2 = *(const float4*)(s2 + base);
    float v2[4] = {V2.x, V2.y, V2.z, V2.w};
    float m1 = -1e30f, m2 = -1e30f;
#pragma unroll
    for (int i = 0; i < 4; ++i) { m1 = fmaxf(m1, v1[i]); m2 = fmaxf(m2, v2[i]); }
    blockReduce2(m1, m2, true, red);
    float e1 = 0.f, e2 = 0.f;
#pragma unroll
    for (int i = 0; i < 4; ++i) {
        v1[i] = __expf(v1[i] - m1); e1 += v1[i];
        v2[i] = __expf(v2[i] - m2); e2 += v2[i];
    }
    blockReduce2(e1, e2, false, red);
    float r1 = __frcp_rn(e1), r2 = __frcp_rn(e2);
    float ent1 = 0.f, ent2 = 0.f;
#pragma unroll
    for (int i = 0; i < 4; ++i) {
        float a1 = og * v1[i] * r1 + gsig * pv[i];
        float a2 = og * v2[i] * r2 + gsig * pv[i];
        v1[i] = a1; v2[i] = a2;
        ent1 -= a1 * __logf(a1 + 1e-8f);
        ent2 -= a2 * __logf(a2 + 1e-8f);
    }
    blockReduce2(ent1, ent2, false, red);
    float h1 = 2.f - 2.f / (1.f + __expf(-tt * ent1));
    float h2 = 2.f - 2.f / (1.f + __expf(-tt * ent2));
    bool fg = (h1 >= h2);
    if (tid == 0) heat_out[(size_t)b * NQ + n] = fg ? h1 : h2;
    float a0 = fg ? v1[0] : v2[0], a1 = fg ? v1[1] : v2[1];
    float a2 = fg ? v1[2] : v2[2], a3 = fg ? v1[3] : v2[3];
    *(__half2*)(g_ach + rowoff + base)     = __floats2half2_rn(a0, a1);
    *(__half2*)(g_ach + rowoff + base + 2) = __floats2half2_rn(a2, a3);
}

// ---------------- launch ----------------
extern "C" void kernel_launch(void* const* d_in, const int* in_sizes, int n_in,
                              void* d_out, int out_size) {
    const float* x      = (const float*)d_in[0];
    const float* y      = (const float*)d_in[1];
    const float* coords = (const float*)d_in[2];
    const float* U      = (const float*)d_in[3];
    const float* S1     = (const float*)d_in[4];
    const float* S2     = (const float*)d_in[5];
    const float* gating = (const float*)d_in[6];
    const float* temp   = (const float*)d_in[7];
    const float* pe     = (const float*)d_in[8];
    float* out  = (float*)d_out;                 // [B,N,D]
    float* heat = out + (size_t)BB * NQ * DD;    // [B,N,1]

    const int SM3   = 122880;  // 3-term NT
    const int SM2   = 92160;   // 2-term NT
    const int SM1   = 61440;   // 1-term NT
    const int SM1BT = 56832;   // 1-term BT
    cudaFuncSetAttribute(k_buildA, cudaFuncAttributeMaxDynamicSharedMemorySize, SM3);
    cudaFuncSetAttribute(k_xk,     cudaFuncAttributeMaxDynamicSharedMemorySize, SM2);
    cudaFuncSetAttribute(k_scores, cudaFuncAttributeMaxDynamicSharedMemorySize, SM1);
    cudaFuncSetAttribute(k_av,     cudaFuncAttributeMaxDynamicSharedMemorySize, SM1BT);

    __half *xh, *yh;
    cudaGetSymbolAddress((void**)&xh, g_xh);
    cudaGetSymbolAddress((void**)&yh, g_yh);

    int n4 = BB * NQ * DD / 4;
    k_flag<<<1, 256>>>(S1, S2);
    k_prepU<<<dim3(DD / 32, DD / 32), dim3(32, 8)>>>(U, S1, S2);
    k_cvt2<<<dim3((n4 + 255) / 256, 2), 256>>>((const float4*)x, (const float4*)y,
                                               (__half2*)xh, (__half2*)yh, n4);
    k_buildA<<<dim3(DD / 128, DD / 128, 8), 512, SM3>>>();
    k_cvtA<<<dim3(DD * DD / 512, 2), 256>>>();
    k_xk    <<<dim3(DD / 128, BB * NQ / 128, 2), 512, SM2>>>();
    k_pos<<<dim3(NQ), 256>>>(coords, pe);
    k_scores<<<dim3(MKV / 128, NQ / 128, BB * 2), 512, SM1>>>();
    k_route <<<dim3(NQ, BB), 256>>>(gating, temp, heat);
    k_av    <<<dim3(DD / 128, NQ / 128, BB), 512, SM1BT>>>(out);
}

// round 16
// speedup vs baseline: 1.0910x; 1.0158x over previous
#include <cuda_runtime.h>
#include <cuda_fp16.h>
#include <cstdint>
#include <cstddef>
#include <math.h>

#define BB   16
#define NQ   1024
#define MKV  1024
#define DD   768
#define SCALE 0.03608439182435161f   // 768^-0.5

// ---------------- scratch (device globals) ----------------
__device__ __half g_Ah[2][DD * DD], g_Al[2][DD * DD];
__device__ float g_Apart[2][4][DD * DD];
__device__ __half g_UTh[DD * DD], g_UTl[DD * DD];
__device__ __half g_UscTh[2][DD * DD], g_UscTl[2][DD * DD];
__device__ __half g_xh[BB * NQ * DD];
__device__ __half g_yh[BB * MKV * DD];
__device__ __half g_xkh[2][BB * NQ * DD];
__device__ float g_pos[NQ * MKV];
__device__ float g_s[(size_t)BB * 2 * NQ * MKV];
__device__ __half g_ach[(size_t)BB * NQ * MKV];
__device__ int g_same;    // 1 iff S1 == S2 exactly
__device__ int g_ident;   // 1 iff S1 == S2 == 1 -> A = U^T U = I (QR-orthogonal U), x_k = x

// ---------------- PTX helpers ----------------
__device__ __forceinline__ unsigned u32smem(const void* p) {
    return (unsigned)__cvta_generic_to_shared(p);
}
#define CP16(dst, src) asm volatile("cp.async.cg.shared.global [%0], [%1], 16;\n" :: "r"(dst), "l"(src))
#define CPCOMMIT() asm volatile("cp.async.commit_group;\n" ::: "memory")
#define CPWAIT1() asm volatile("cp.async.wait_group 1;\n" ::: "memory")
#define LDSM4(R0,R1,R2,R3,addr) \
    asm volatile("ldmatrix.sync.aligned.m8n8.x4.shared.b16 {%0,%1,%2,%3}, [%4];" \
                 : "=r"(R0),"=r"(R1),"=r"(R2),"=r"(R3) : "r"(addr))
#define LDSM4T(R0,R1,R2,R3,addr) \
    asm volatile("ldmatrix.sync.aligned.m8n8.x4.trans.shared.b16 {%0,%1,%2,%3}, [%4];" \
                 : "=r"(R0),"=r"(R1),"=r"(R2),"=r"(R3) : "r"(addr))
#define MMA(C,A,B) \
    asm volatile("mma.sync.aligned.m16n8k16.row.col.f32.f16.f16.f32 " \
                 "{%0,%1,%2,%3},{%4,%5,%6,%7},{%8,%9},{%0,%1,%2,%3};" \
                 : "+f"((C)[0]),"+f"((C)[1]),"+f"((C)[2]),"+f"((C)[3]) \
                 : "r"((A)[0]),"r"((A)[1]),"r"((A)[2]),"r"((A)[3]),"r"((B)[0]),"r"((B)[1]))

__device__ __forceinline__ void split2(float a, float b, __half2& hi, __half2& lo) {
    __half h0 = __float2half_rn(a), h1 = __float2half_rn(b);
    __half l0 = __float2half_rn(a - __half2float(h0));
    __half l1 = __float2half_rn(b - __half2float(h1));
    hi = __halves2half2(h0, h1);
    lo = __halves2half2(l0, l1);
}

// ---------------- fp16-split HMMA mainloop, K-chunk 32 ----------------
// Block tile 128x128, 512 threads (16 warps, 4Mx4N), 3-stage cp.async pipeline.
// TERMS==1: C = Ah*Bh.  TERMS==2: + Ah*Bl.  TERMS==3: + Al*Bh.

template<bool BT, int TERMS>
__device__ __forceinline__ void gemm_main(
    const __half* __restrict__ Ah, const __half* __restrict__ Al, int lda,
    const __half* __restrict__ Bh, const __half* __restrict__ Bl, int ldb,
    int K, int row0, int col0, float acc[2][4][4])
{
    extern __shared__ char smc[];
    const unsigned BSTG = BT ? 8704u : 10240u;
    const unsigned oAl = 30720u;
    const unsigned oBh = (TERMS == 3) ? 61440u : 30720u;
    unsigned sb = u32smem(smc);
    int tid = threadIdx.x;
    int KT = K >> 5;

    auto load_stage = [&](int s, int kt) {
        if (kt < KT) {
            int k0 = kt << 5;
            {
                int rr = tid >> 2, ch = tid & 3;
                size_t go = (size_t)(row0 + rr) * lda + k0 + ch * 8;
                unsigned d = sb + (unsigned)(s * 10240 + rr * 80 + ch * 16);
                CP16(d, Ah + go);
                if (TERMS == 3) { CP16(d + oAl, Al + go); }
            }
            if (BT) {
                int kr = tid >> 4, ch = tid & 15;
                size_t go = (size_t)(k0 + kr) * ldb + col0 + ch * 8;
                unsigned d = sb + oBh + (unsigned)(s * 8704 + kr * 272 + ch * 16);
                CP16(d, Bh + go);
                if (TERMS >= 2) { CP16(d + 3u * 8704u, Bl + go); }
            } else {
                int rr = tid >> 2, ch = tid & 3;
                size_t go = (size_t)(col0 + rr) * ldb + k0 + ch * 8;
                unsigned d = sb + oBh + (unsigned)(s * 10240 + rr * 80 + ch * 16);
                CP16(d, Bh + go);
                if (TERMS >= 2) { CP16(d + 3u * 10240u, Bl + go); }
            }
        }
        CPCOMMIT();
    };

    load_stage(0, 0);
    load_stage(1, 1);

    int lane = tid & 31, wid = tid >> 5;
    int wm = wid & 3, wn = wid >> 2;
    int r = lane & 7, sel = lane >> 3, sx = sel & 1, sy = sel >> 1;

    for (int kt = 0; kt < KT; ++kt) {
        CPWAIT1();
        __syncthreads();
        load_stage((kt + 2) % 3, kt + 2);
        int s = kt % 3;
        unsigned aBase = sb + (unsigned)(s * 10240);
        unsigned bBase = sb + oBh + (unsigned)s * BSTG;
#pragma unroll
        for (int h = 0; h < 2; ++h) {
            unsigned ah[2][4], al[2][4], bh[4][2], bl[4][2];
#pragma unroll
            for (int mt = 0; mt < 2; ++mt) {
                unsigned off = (unsigned)((wm * 32 + mt * 16 + r + sx * 8) * 80 + h * 32 + sy * 16);
                LDSM4(ah[mt][0], ah[mt][1], ah[mt][2], ah[mt][3], aBase + off);
                if (TERMS == 3) {
                    LDSM4(al[mt][0], al[mt][1], al[mt][2], al[mt][3], aBase + oAl + off);
                }
            }
#pragma unroll
            for (int p = 0; p < 2; ++p) {
                unsigned t0, t1, t2, t3;
                if (BT) {
                    unsigned off = (unsigned)((h * 16 + r + sx * 8) * 272 + (wn * 32 + p * 16 + sy * 8) * 2);
                    LDSM4T(t0, t1, t2, t3, bBase + off);
                    bh[2*p][0] = t0; bh[2*p][1] = t1; bh[2*p+1][0] = t2; bh[2*p+1][1] = t3;
                    if (TERMS >= 2) {
                        LDSM4T(t0, t1, t2, t3, bBase + 3u * 8704u + off);
                        bl[2*p][0] = t0; bl[2*p][1] = t1; bl[2*p+1][0] = t2; bl[2*p+1][1] = t3;
                    }
                } else {
                    unsigned off = (unsigned)((wn * 32 + p * 16 + r + sy * 8) * 80 + h * 32 + sx * 16);
                    LDSM4(t0, t1, t2, t3, bBase + off);
                    bh[2*p][0] = t0; bh[2*p][1] = t1; bh[2*p+1][0] = t2; bh[2*p+1][1] = t3;
                    if (TERMS >= 2) {
                        LDSM4(t0, t1, t2, t3, bBase + 3u * 10240u + off);
                        bl[2*p][0] = t0; bl[2*p][1] = t1; bl[2*p+1][0] = t2; bl[2*p+1][1] = t3;
                    }
                }
            }
#pragma unroll
            for (int mt = 0; mt < 2; ++mt)
#pragma unroll
                for (int nt = 0; nt < 4; ++nt) {
                    MMA(acc[mt][nt], ah[mt], bh[nt]);
                    if (TERMS >= 2) { MMA(acc[mt][nt], ah[mt], bl[nt]); }
                    if (TERMS == 3) { MMA(acc[mt][nt], al[mt], bh[nt]); }
                }
        }
    }
}

// ---------------- small kernels ----------------
__global__ void k_flag(const float* __restrict__ S1, const float* __restrict__ S2) {
    __shared__ int ok, one;
    if (threadIdx.x == 0) { ok = 1; one = 1; }
    __syncthreads();
    for (int i = threadIdx.x; i < DD; i += blockDim.x) {
        float a = S1[i], b = S2[i];
        if (a != b) atomicAnd(&ok, 0);
        if (a != 1.0f || b != 1.0f) atomicAnd(&one, 0);
    }
    __syncthreads();
    if (threadIdx.x == 0) { g_same = ok; g_ident = one; }
}

// merged hi-only convert for x and y (grid.y selects)
__global__ void k_cvt2(const float4* __restrict__ xs, const float4* __restrict__ ys,
                       __half2* __restrict__ dx, __half2* __restrict__ dy, int n4) {
    int i = blockIdx.x * blockDim.x + threadIdx.x;
    if (i >= n4) return;
    const float4* s = blockIdx.y ? ys : xs;
    __half2* d = blockIdx.y ? dy : dx;
    float4 v = s[i];
    d[2 * i]     = __floats2half2_rn(v.x, v.y);
    d[2 * i + 1] = __floats2half2_rn(v.z, v.w);
}

__global__ void k_prepU(const float* __restrict__ U, const float* __restrict__ S1,
                        const float* __restrict__ S2) {
    if (g_ident) return;
    __shared__ float t[32][33];
    __shared__ float s2a[32], s2b[32];
    int j0 = blockIdx.x * 32, t0 = blockIdx.y * 32;
    int tx = threadIdx.x, ty = threadIdx.y;
    if (ty == 0) {
        float s = S1[t0 + tx]; s2a[tx] = s * s;
        float q = S2[t0 + tx]; s2b[tx] = q * q;
    }
#pragma unroll
    for (int r = 0; r < 4; ++r)
        t[ty * 4 + r][tx] = U[(size_t)(t0 + ty * 4 + r) * DD + j0 + tx];
    __syncthreads();
    int same = g_same;
#pragma unroll
    for (int r = 0; r < 4; ++r) {
        int jr = ty * 4 + r;
        float v = t[tx][jr];
        size_t o = (size_t)(j0 + jr) * DD + t0 + tx;
        __half h = __float2half_rn(v);
        g_UTh[o] = h;
        g_UTl[o] = __float2half_rn(v - __half2float(h));
        float va = v * s2a[tx];
        __half ha = __float2half_rn(va);
        g_UscTh[0][o] = ha;
        g_UscTl[0][o] = __float2half_rn(va - __half2float(ha));
        if (!same) {
            float vb = v * s2b[tx];
            __half hb = __float2half_rn(vb);
            g_UscTh[1][o] = hb;
            g_UscTl[1][o] = __float2half_rn(vb - __half2float(hb));
        }
    }
}

__global__ void k_pos(const float* __restrict__ coords, const float* __restrict__ pe) {
    int n = blockIdx.x;
    int tid = threadIdx.x;
    __shared__ float red[16];
    float p[6];
#pragma unroll
    for (int c = 0; c < 6; ++c) p[c] = pe[n * 6 + c];
    float v[4];
#pragma unroll
    for (int i = 0; i < 4; ++i) {
        int m = tid + (i << 8);
        const float* cr = coords + ((size_t)n * MKV + m) * 6;
        v[i] = cr[0]*p[0] + cr[1]*p[1] + cr[2]*p[2] + cr[3]*p[3] + cr[4]*p[4] + cr[5]*p[5];
    }
    float mx = fmaxf(fmaxf(v[0], v[1]), fmaxf(v[2], v[3]));
#pragma unroll
    for (int o = 16; o; o >>= 1) mx = fmaxf(mx, __shfl_xor_sync(0xffffffffu, mx, o));
    int w = tid >> 5, lane = tid & 31;
    if (lane == 0) red[w] = mx;
    __syncthreads();
    mx = red[0];
#pragma unroll
    for (int i = 1; i < 8; ++i) mx = fmaxf(mx, red[i]);
    __syncthreads();
    float e = 0.f;
#pragma unroll
    for (int i = 0; i < 4; ++i) { v[i] = __expf(v[i] - mx); e += v[i]; }
#pragma unroll
    for (int o = 16; o; o >>= 1) e += __shfl_xor_sync(0xffffffffu, e, o);
    if (lane == 0) red[w] = e;
    __syncthreads();
    e = 0.f;
#pragma unroll
    for (int i = 0; i < 8; ++i) e += red[i];
    float rinv = __frcp_rn(e);
#pragma unroll
    for (int i = 0; i < 4; ++i) {
        int m = tid + (i << 8);
        g_pos[(size_t)n * MKV + m] = v[i] * rinv;
    }
}

// ---------------- GEMM kernels ----------------

// A_k partials: split-K (4x192), 3-term
__global__ void __launch_bounds__(512, 1) k_buildA() {
    if (g_ident) return;
    int z = blockIdx.z;
    int k2 = z >> 2, ks = z & 3;
    if (k2 == 1 && g_same) return;
    int row0 = blockIdx.y << 7, col0 = blockIdx.x << 7;
    float acc[2][4][4] = {};
    gemm_main<false, 3>(g_UscTh[k2] + ks * 192, g_UscTl[k2] + ks * 192, DD,
                        g_UTh + ks * 192, g_UTl + ks * 192, DD,
                        192, row0, col0, acc);
    int lane = threadIdx.x & 31, wid = threadIdx.x >> 5;
    int wm = wid & 3, wn = wid >> 2, g = lane >> 2, tg = lane & 3;
    float* P = g_Apart[k2][ks];
#pragma unroll
    for (int mt = 0; mt < 2; ++mt)
#pragma unroll
        for (int nt = 0; nt < 4; ++nt) {
            int row = row0 + wm * 32 + mt * 16 + g;
            int col = col0 + wn * 32 + nt * 8 + tg * 2;
#pragma unroll
            for (int hh = 0; hh < 2; ++hh) {
                float2 v = make_float2(acc[mt][nt][2 * hh], acc[mt][nt][2 * hh + 1]);
                *(float2*)(P + (size_t)(row + hh * 8) * DD + col) = v;
            }
        }
}

__global__ void k_cvtA() {
    if (g_ident) return;
    int k2 = blockIdx.y;
    if (k2 == 1 && g_same) return;
    int i = blockIdx.x * blockDim.x + threadIdx.x;
    int idx = i * 2;
    float2 a = *(const float2*)(g_Apart[k2][0] + idx);
    float2 b = *(const float2*)(g_Apart[k2][1] + idx);
    float2 c = *(const float2*)(g_Apart[k2][2] + idx);
    float2 d = *(const float2*)(g_Apart[k2][3] + idx);
    float v0 = a.x + b.x + c.x + d.x;
    float v1 = a.y + b.y + c.y + d.y;
    __half2 hi, lo;
    split2(v0, v1, hi, lo);
    *(__half2*)(g_Ah[k2] + idx) = hi;
    *(__half2*)(g_Al[k2] + idx) = lo;
}

// x_k = x @ A_k — 2-term (general path only)
__global__ void __launch_bounds__(512, 2) k_xk() {
    if (g_ident) return;
    int z = blockIdx.z;
    if (z == 1 && g_same) return;
    int row0 = blockIdx.y << 7, col0 = blockIdx.x << 7;
    float acc[2][4][4] = {};
    gemm_main<false, 2>(g_xh, g_xh, DD,
                        g_Ah[z], g_Al[z], DD,
                        DD, row0, col0, acc);
    int lane = threadIdx.x & 31, wid = threadIdx.x >> 5;
    int wm = wid & 3, wn = wid >> 2, g = lane >> 2, tg = lane & 3;
    __half* Ch = g_xkh[z];
#pragma unroll
    for (int mt = 0; mt < 2; ++mt)
#pragma unroll
        for (int nt = 0; nt < 4; ++nt) {
            int row = row0 + wm * 32 + mt * 16 + g;
            int col = col0 + wn * 32 + nt * 8 + tg * 2;
#pragma unroll
            for (int hh = 0; hh < 2; ++hh) {
                size_t idx = (size_t)(row + hh * 8) * DD + col;
                *(__half2*)(Ch + idx) =
                    __floats2half2_rn(acc[mt][nt][2 * hh], acc[mt][nt][2 * hh + 1]);
            }
        }
}

// scores (NT): s = scale * x_k[b] @ y[b]^T — 1-term, chunk 32
__global__ void __launch_bounds__(512, 2) k_scores() {
    int z = blockIdx.z; int b = z >> 1; int k2 = z & 1;
    if (k2 == 1 && g_same) return;
    int row0 = blockIdx.y << 7, col0 = blockIdx.x << 7;
    const __half* A = g_ident ? (g_xh + (size_t)b * NQ * DD)
                              : (g_xkh[k2] + (size_t)b * NQ * DD);
    float acc[2][4][4] = {};
    gemm_main<false, 1>(A, A, DD,
                        g_yh + (size_t)b * MKV * DD, g_yh + (size_t)b * MKV * DD, DD,
                        DD, row0, col0, acc);
    int lane = threadIdx.x & 31, wid = threadIdx.x >> 5;
    int wm = wid & 3, wn = wid >> 2, g = lane >> 2, tg = lane & 3;
    float* C = g_s + (size_t)z * NQ * MKV;
#pragma unroll
    for (int mt = 0; mt < 2; ++mt)
#pragma unroll
        for (int nt = 0; nt < 4; ++nt) {
            int row = row0 + wm * 32 + mt * 16 + g;
            int col = col0 + wn * 32 + nt * 8 + tg * 2;
#pragma unroll
            for (int hh = 0; hh < 2; ++hh) {
                float2 v = make_float2(acc[mt][nt][2 * hh] * SCALE, acc[mt][nt][2 * hh + 1] * SCALE);
                *(float2*)(C + (size_t)(row + hh * 8) * MKV + col) = v;
            }
        }
}

// out = attn_c @ y (NN) — 1-term, chunk 32
__global__ void __launch_bounds__(512, 2) k_av(float* __restrict__ out) {
    int b = blockIdx.z;
    int row0 = blockIdx.y << 7, col0 = blockIdx.x << 7;
    float acc[2][4][4] = {};
    gemm_main<true, 1>(g_ach + (size_t)b * NQ * MKV, g_ach + (size_t)b * NQ * MKV, MKV,
                       g_yh + (size_t)b * MKV * DD, g_yh + (size_t)b * MKV * DD, DD,
                       MKV, row0, col0, acc);
    int lane = threadIdx.x & 31, wid = threadIdx.x >> 5;
    int wm = wid & 3, wn = wid >> 2, g = lane >> 2, tg = lane & 3;
    float* C = out + (size_t)b * NQ * DD;
#pragma unroll
    for (int mt = 0; mt < 2; ++mt)
#pragma unroll
        for (int nt = 0; nt < 4; ++nt) {
            int row = row0 + wm * 32 + mt * 16 + g;
            int col = col0 + wn * 32 + nt * 8 + tg * 2;
#pragma unroll
            for (int hh = 0; hh < 2; ++hh) {
                float2 v = make_float2(acc[mt][nt][2 * hh], acc[mt][nt][2 * hh + 1]);
                *(float2*)(C + (size_t)(row + hh * 8) * DD + col) = v;
            }
        }
}

// ---------------- K4: softmax + mix + entropy + route ----------------
__device__ __forceinline__ void blockReduce2(float& a, float& b, bool domax, float* red) {
#pragma unroll
    for (int o = 16; o; o >>= 1) {
        float ta = __shfl_xor_sync(0xffffffffu, a, o);
        float tb = __shfl_xor_sync(0xffffffffu, b, o);
        if (domax) { a = fmaxf(a, ta); b = fmaxf(b, tb); }
        else       { a += ta;          b += tb; }
    }
    int w = threadIdx.x >> 5, lane = threadIdx.x & 31;
    __syncthreads();
    if (lane == 0) { red[w] = a; red[8 + w] = b; }
    __syncthreads();
    a = red[0]; b = red[8];
#pragma unroll
    for (int i = 1; i < 8; ++i) {
        if (domax) { a = fmaxf(a, red[i]); b = fmaxf(b, red[8 + i]); }
        else       { a += red[i];          b += red[8 + i]; }
    }
}

__global__ void k_route(const float* __restrict__ gate, const float* __restrict__ temp,
                        float* __restrict__ heat_out) {
    int n = blockIdx.x, b = blockIdx.y;
    int tid = threadIdx.x;
    __shared__ float red[16];
    int same = g_same;
    const float* s1 = g_s + ((size_t)(b * 2 + 0) * NQ + n) * MKV;
    const float* s2 = g_s + ((size_t)(b * 2 + 1) * NQ + n) * MKV;
    const float* pp = g_pos + (size_t)n * MKV;
    int base = tid * 4;
    float4 V1 = *(const float4*)(s1 + base);
    float4 PV = *(const float4*)(pp + base);
    float v1[4] = {V1.x, V1.y, V1.z, V1.w};
    float pv[4] = {PV.x, PV.y, PV.z, PV.w};
    float gg = gate[0];
    float gsig = 1.f / (1.f + __expf(-gg));
    float og = 1.f - gsig;
    float tt = temp[0];
    size_t rowoff = ((size_t)b * NQ + n) * MKV;

    if (same) {
        float m1 = -1e30f, dummy = -1e30f;
#pragma unroll
        for (int i = 0; i < 4; ++i) m1 = fmaxf(m1, v1[i]);
        blockReduce2(m1, dummy, true, red);
        float e1 = 0.f, d2 = 0.f;
#pragma unroll
        for (int i = 0; i < 4; ++i) { v1[i] = __expf(v1[i] - m1); e1 += v1[i]; }
        blockReduce2(e1, d2, false, red);
        float r1 = __frcp_rn(e1);
        float ent1 = 0.f, d3 = 0.f;
#pragma unroll
        for (int i = 0; i < 4; ++i) {
            float a1 = og * v1[i] * r1 + gsig * pv[i];
            v1[i] = a1;
            ent1 -= a1 * __logf(a1 + 1e-8f);
        }
        blockReduce2(ent1, d3, false, red);
        float h1 = 2.f - 2.f / (1.f + __expf(-tt * ent1));
        if (tid == 0) heat_out[(size_t)b * NQ + n] = h1;
        *(__half2*)(g_ach + rowoff + base)     = __floats2half2_rn(v1[0], v1[1]);
        *(__half2*)(g_ach + rowoff + base + 2) = __floats2half2_rn(v1[2], v1[3]);
        return;
    }

    float4 V2 = *(const float4*)(s2 + base);
    float v2[4] = {V2.x, V2.y, V2.z, V2.w};
    float m1 = -1e30f, m2 = -1e30f;
#pragma unroll
    for (int i = 0; i < 4; ++i) { m1 = fmaxf(m1, v1[i]); m2 = fmaxf(m2, v2[i]); }
    blockReduce2(m1, m2, true, red);
    float e1 = 0.f, e2 = 0.f;
#pragma unroll
    for (int i = 0; i < 4; ++i) {
        v1[i] = __expf(v1[i] - m1); e1 += v1[i];
        v2[i] = __expf(v2[i] - m2); e2 += v2[i];
    }
    blockReduce2(e1, e2, false, red);
    float r1 = __frcp_rn(e1), r2 = __frcp_rn(e2);
    float ent1 = 0.f, ent2 = 0.f;
#pragma unroll
    for (int i = 0; i < 4; ++i) {
        float a1 = og * v1[i] * r1 + gsig * pv[i];
        float a2 = og * v2[i] * r2 + gsig * pv[i];
        v1[i] = a1; v2[i] = a2;
        ent1 -= a1 * __logf(a1 + 1e-8f);
        ent2 -= a2 * __logf(a2 + 1e-8f);
    }
    blockReduce2(ent1, ent2, false, red);
    float h1 = 2.f - 2.f / (1.f + __expf(-tt * ent1));
    float h2 = 2.f - 2.f / (1.f + __expf(-tt * ent2));
    bool fg = (h1 >= h2);
    if (tid == 0) heat_out[(size_t)b * NQ + n] = fg ? h1 : h2;
    float a0 = fg ? v1[0] : v2[0], a1 = fg ? v1[1] : v2[1];
    float a2 = fg ? v1[2] : v2[2], a3 = fg ? v1[3] : v2[3];
    *(__half2*)(g_ach + rowoff + base)     = __floats2half2_rn(a0, a1);
    *(__half2*)(g_ach + rowoff + base + 2) = __floats2half2_rn(a2, a3);
}

// ---------------- launch ----------------
extern "C" void kernel_launch(void* const* d_in, const int* in_sizes, int n_in,
                              void* d_out, int out_size) {
    const float* x      = (const float*)d_in[0];
    const float* y      = (const float*)d_in[1];
    const float* coords = (const float*)d_in[2];
    const float* U      = (const float*)d_in[3];
    const float* S1     = (const float*)d_in[4];
    const float* S2     = (const float*)d_in[5];
    const float* gating = (const float*)d_in[6];
    const float* temp   = (const float*)d_in[7];
    const float* pe     = (const float*)d_in[8];
    float* out  = (float*)d_out;                 // [B,N,D]
    float* heat = out + (size_t)BB * NQ * DD;    // [B,N,1]

    const int SM3   = 122880;  // 3-term NT
    const int SM2   = 92160;   // 2-term NT
    const int SM1   = 61440;   // 1-term NT
    const int SM1BT = 56832;   // 1-term BT
    cudaFuncSetAttribute(k_buildA, cudaFuncAttributeMaxDynamicSharedMemorySize, SM3);
    cudaFuncSetAttribute(k_xk,     cudaFuncAttributeMaxDynamicSharedMemorySize, SM2);
    cudaFuncSetAttribute(k_scores, cudaFuncAttributeMaxDynamicSharedMemorySize, SM1);
    cudaFuncSetAttribute(k_av,     cudaFuncAttributeMaxDynamicSharedMemorySize, SM1BT);

    __half *xh, *yh;
    cudaGetSymbolAddress((void**)&xh, g_xh);
    cudaGetSymbolAddress((void**)&yh, g_yh);

    int n4 = BB * NQ * DD / 4;
    cudaStream_t s2 = cudaStreamPerThread;   // pre-existing stream; no creation

    // events (host objects; created per call, intentionally not destroyed to
    // avoid invalidating an in-progress capture; ~2 handles per call)
    cudaEvent_t eF, eA;
    cudaEventCreateWithFlags(&eF, cudaEventDisableTiming);
    cudaEventCreateWithFlags(&eA, cudaEventDisableTiming);

    // main stream: flag first (everything reads g_same/g_ident)
    k_flag<<<1, 256>>>(S1, S2);
    cudaEventRecord(eF, 0);

    // side stream: pos + A-matrix chain (dead in ident mode), forked after flag
    cudaStreamWaitEvent(s2, eF, 0);
    k_pos<<<dim3(NQ), 256, 0, s2>>>(coords, pe);
    k_prepU<<<dim3(DD / 32, DD / 32), dim3(32, 8), 0, s2>>>(U, S1, S2);
    k_buildA<<<dim3(DD / 128, DD / 128, 8), 512, SM3, s2>>>();
    k_cvtA<<<dim3(DD * DD / 512, 2), 256, 0, s2>>>();
    cudaEventRecord(eA, s2);

    // main stream: conversions overlap the side chain
    k_cvt2<<<dim3((n4 + 255) / 256, 2), 256>>>((const float4*)x, (const float4*)y,
                                               (__half2*)xh, (__half2*)yh, n4);
    cudaStreamWaitEvent(0, eA, 0);           // join: xk needs A; route needs pos
    k_xk    <<<dim3(DD / 128, BB * NQ / 128, 2), 512, SM2>>>();
    k_scores<<<dim3(MKV / 128, NQ / 128, BB * 2), 512, SM1>>>();
    k_route <<<dim3(NQ, BB), 256>>>(gating, temp, heat);
    k_av    <<<dim3(DD / 128, NQ / 128, BB), 512, SM1BT>>>(out);
}